// round 2
// baseline (speedup 1.0000x reference)
#include <cuda_runtime.h>
#include <cuda_bf16.h>
#include <math_constants.h>

// Problem constants (fixed by the dataset)
#define NNODES   100000
#define EEDGES   1600000
#define TEDGES   (EEDGES + NNODES)   // edges + self loops
#define NEG_SLOPE 0.2f
#define HEADS 4

// ---------------------------------------------------------------------------
// Device scratch (static allocation — no cudaMalloc allowed)
// ---------------------------------------------------------------------------
__device__ float g_xl[NNODES * 256];     // source-side transform (layer max D=256)
__device__ float g_xr[NNODES * 256];     // target-side transform
__device__ float g_h [NNODES * 64];      // layer-1 output
__device__ float g_agg[NNODES * 256];    // aggregation buffer
__device__ float g_score[TEDGES * HEADS];// per-edge scores / exp
__device__ float g_max [NNODES * HEADS]; // segment max
__device__ float g_den [NNODES * HEADS]; // segment sum of exp
__device__ int   g_src[TEDGES];          // int32 src (incl. self loops)
__device__ int   g_dst[TEDGES];          // int32 dst (incl. self loops)
__device__ int   g_is64;                 // dtype flag for edge_index buffer

static inline int cdiv(int a, int b) { return (a + b - 1) / b; }

// ---------------------------------------------------------------------------
// Float atomic max (sign-split trick; correct for all finite floats, -inf init)
// ---------------------------------------------------------------------------
__device__ __forceinline__ void atomicMaxF(float* addr, float value) {
    if (value >= 0.f)
        atomicMax((int*)addr, __float_as_int(value));
    else
        atomicMin((unsigned int*)addr, __float_as_uint(value));
}

// ---------------------------------------------------------------------------
// Edge-index dtype detection: if the buffer is int64, the first K values read
// as int64 are all in [0, N). If it is int32, an int64 read merges two
// indices (lo + hi*2^32) and lands far outside [0, N) with prob ~1.
// ---------------------------------------------------------------------------
__global__ void detect_kernel(const void* ei, int nCheck, long long nNodes) {
    const long long* p = (const long long*)ei;
    int ok = 1;
    for (int i = 0; i < nCheck; i++) {
        long long v = p[i];
        if (v < 0 || v >= nNodes) { ok = 0; break; }
    }
    g_is64 = ok;
}

// Convert edge_index (either dtype) to int32 src/dst arrays with self loops.
__global__ void convert_edges_kernel(const void* ei, int E, int Nn) {
    int i = blockIdx.x * blockDim.x + threadIdx.x;
    int total = E + Nn;
    if (i >= total) return;
    if (i < E) {
        if (g_is64) {
            const long long* p = (const long long*)ei;
            g_src[i] = (int)p[i];
            g_dst[i] = (int)p[E + i];
        } else {
            const int* p = (const int*)ei;
            g_src[i] = p[i];
            g_dst[i] = p[E + i];
        }
    } else {
        int n = i - E;
        g_src[i] = n;
        g_dst[i] = n;
    }
}

// ---------------------------------------------------------------------------
// Init: zero agg region, zero denom, -inf max
// ---------------------------------------------------------------------------
__global__ void init_kernel(int nAgg, int nNH) {
    int i = blockIdx.x * blockDim.x + threadIdx.x;
    if (i < nAgg) g_agg[i] = 0.f;
    if (i < nNH) { g_den[i] = 0.f; g_max[i] = -CUDART_INF_F; }
}

// ---------------------------------------------------------------------------
// Tiled fp32 GEMM: C[M,Ncol] = A[M,K] @ W[K,Ncol] + bias   (K%16==0, Ncol%64==0)
// BM=64, BN=64, BK=16, 256 threads, 4x4 micro-tile
// ---------------------------------------------------------------------------
__global__ void gemm_bias_kernel(const float* __restrict__ A,
                                 const float* __restrict__ W,
                                 const float* __restrict__ bias,
                                 float* __restrict__ C,
                                 int M, int K, int Ncol) {
    __shared__ float As[16][65];
    __shared__ float Ws[16][65];
    const int tid = threadIdx.x;
    const int row0 = blockIdx.y * 64;
    const int col0 = blockIdx.x * 64;
    const int tx = tid & 15, ty = tid >> 4;
    float acc[4][4] = {};

    for (int k0 = 0; k0 < K; k0 += 16) {
        {   // A tile: 64 rows x 16 cols (float4 per thread)
            int r = tid >> 2, c4 = (tid & 3) * 4;
            int row = row0 + r;
            float4 v = make_float4(0.f, 0.f, 0.f, 0.f);
            if (row < M)
                v = *reinterpret_cast<const float4*>(A + (size_t)row * K + k0 + c4);
            As[c4 + 0][r] = v.x; As[c4 + 1][r] = v.y;
            As[c4 + 2][r] = v.z; As[c4 + 3][r] = v.w;
        }
        {   // W tile: 16 rows x 64 cols (float4 per thread)
            int kk = tid >> 4, c4 = (tid & 15) * 4;
            float4 v = *reinterpret_cast<const float4*>(W + (size_t)(k0 + kk) * Ncol + col0 + c4);
            Ws[kk][c4 + 0] = v.x; Ws[kk][c4 + 1] = v.y;
            Ws[kk][c4 + 2] = v.z; Ws[kk][c4 + 3] = v.w;
        }
        __syncthreads();
        #pragma unroll
        for (int kk = 0; kk < 16; kk++) {
            float am[4], wn[4];
            #pragma unroll
            for (int i = 0; i < 4; i++) am[i] = As[kk][ty * 4 + i];
            #pragma unroll
            for (int j = 0; j < 4; j++) wn[j] = Ws[kk][tx * 4 + j];
            #pragma unroll
            for (int i = 0; i < 4; i++)
                #pragma unroll
                for (int j = 0; j < 4; j++)
                    acc[i][j] += am[i] * wn[j];
        }
        __syncthreads();
    }
    #pragma unroll
    for (int i = 0; i < 4; i++) {
        int row = row0 + ty * 4 + i;
        if (row >= M) continue;
        #pragma unroll
        for (int j = 0; j < 4; j++) {
            int col = col0 + tx * 4 + j;
            C[(size_t)row * Ncol + col] = acc[i][j] + bias[col];
        }
    }
}

// ---------------------------------------------------------------------------
// Vector load helper (PE contiguous floats, PE in {2, 8}, aligned)
// ---------------------------------------------------------------------------
template<int PE>
__device__ __forceinline__ void loadVec(const float* __restrict__ p, float* v) {
    if constexpr (PE % 4 == 0) {
        #pragma unroll
        for (int j = 0; j < PE / 4; j++) {
            float4 t = __ldg(reinterpret_cast<const float4*>(p) + j);
            v[j * 4 + 0] = t.x; v[j * 4 + 1] = t.y;
            v[j * 4 + 2] = t.z; v[j * 4 + 3] = t.w;
        }
    } else {
        float2 t = __ldg(reinterpret_cast<const float2*>(p));
        v[0] = t.x; v[1] = t.y;
    }
}

// ---------------------------------------------------------------------------
// Pass A: per-edge attention score, atomicMax over dst, store score
// One warp per edge; 8 lanes per head; PE = D/32 features per lane (contiguous)
// ---------------------------------------------------------------------------
template<int CC>
__global__ void edge_score_kernel(int total, const float* __restrict__ att) {
    constexpr int D = HEADS * CC;
    constexpr int PE = D / 32;
    int gw = (blockIdx.x * blockDim.x + threadIdx.x) >> 5;
    int lane = threadIdx.x & 31;
    if (gw >= total) return;

    int s = __ldg(g_src + gw);
    int d = __ldg(g_dst + gw);

    const float* xl = g_xl + (size_t)s * D;
    const float* xr = g_xr + (size_t)d * D;
    int f0 = lane * PE;

    float vl[PE], vr[PE];
    loadVec<PE>(xl + f0, vl);
    loadVec<PE>(xr + f0, vr);

    float partial = 0.f;
    #pragma unroll
    for (int j = 0; j < PE; j++) {
        float v = vl[j] + vr[j];
        v = (v > 0.f) ? v : NEG_SLOPE * v;
        partial += __ldg(att + f0 + j) * v;
    }
    // reduce within 8-lane head groups
    #pragma unroll
    for (int off = 4; off; off >>= 1)
        partial += __shfl_down_sync(0xffffffffu, partial, off);

    if ((lane & 7) == 0) {
        int h = lane >> 3;
        g_score[(size_t)gw * HEADS + h] = partial;
        atomicMaxF(&g_max[d * HEADS + h], partial);
    }
}

// ---------------------------------------------------------------------------
// Pass B: exp(score - max[dst]); atomicAdd denom; overwrite score with exp
// One thread per (edge, head)
// ---------------------------------------------------------------------------
__global__ void edge_softmax_kernel(int total) {
    int idx = blockIdx.x * blockDim.x + threadIdx.x;
    if (idx >= total * HEADS) return;
    int e = idx >> 2, h = idx & 3;
    int d = __ldg(g_dst + e);
    float ex = __expf(g_score[idx] - g_max[d * HEADS + h]);
    g_score[idx] = ex;
    atomicAdd(&g_den[d * HEADS + h], ex);
}

// ---------------------------------------------------------------------------
// Pass C: agg[dst] += alpha * xl[src]  (one warp per edge)
// ---------------------------------------------------------------------------
template<int CC>
__global__ void edge_agg_kernel(int total) {
    constexpr int D = HEADS * CC;
    constexpr int PE = D / 32;
    int gw = (blockIdx.x * blockDim.x + threadIdx.x) >> 5;
    int lane = threadIdx.x & 31;
    if (gw >= total) return;

    int s = __ldg(g_src + gw);
    int d = __ldg(g_dst + gw);

    int h = lane >> 3;
    float alpha = g_score[(size_t)gw * HEADS + h] /
                  (g_den[d * HEADS + h] + 1e-16f);

    const float* xl = g_xl + (size_t)s * D;
    float* agg = g_agg + (size_t)d * D;
    int f0 = lane * PE;
    float v[PE];
    loadVec<PE>(xl + f0, v);
    #pragma unroll
    for (int j = 0; j < PE; j++)
        atomicAdd(&agg[f0 + j], alpha * v[j]);
}

// ---------------------------------------------------------------------------
// Finalize layer 1: h = relu(agg + bo1)   (concat layout already matches)
// ---------------------------------------------------------------------------
__global__ void finalize1_kernel(const float* __restrict__ bo, int Nn) {
    int i = blockIdx.x * blockDim.x + threadIdx.x;
    if (i >= Nn * 64) return;
    float v = g_agg[i] + bo[i & 63];
    g_h[i] = (v > 0.f) ? v : 0.f;
}

// ---------------------------------------------------------------------------
// Finalize layer 2: out[n,c] = relu(mean_h(agg[n,h,c]) + bo2[c])
// ---------------------------------------------------------------------------
__global__ void finalize2_kernel(float* __restrict__ out,
                                 const float* __restrict__ bo, int Nn) {
    int i = blockIdx.x * blockDim.x + threadIdx.x;
    if (i >= Nn * 64) return;
    int n = i >> 6, c = i & 63;
    const float* a = g_agg + (size_t)n * 256;
    float s = a[c] + a[64 + c] + a[128 + c] + a[192 + c];
    float v = 0.25f * s + bo[c];
    out[i] = (v > 0.f) ? v : 0.f;
}

// ---------------------------------------------------------------------------
// Host launcher
// ---------------------------------------------------------------------------
extern "C" void kernel_launch(void* const* d_in, const int* in_sizes, int n_in,
                              void* d_out, int out_size) {
    const float* x   = (const float*)d_in[0];
    const void*  ei  = d_in[1];             // int32 or int64, detected on device
    // d_in[2] = frame_mask (unused; all true)
    const float* Wl1 = (const float*)d_in[3];
    const float* bl1 = (const float*)d_in[4];
    const float* Wr1 = (const float*)d_in[5];
    const float* br1 = (const float*)d_in[6];
    const float* att1= (const float*)d_in[7];
    const float* bo1 = (const float*)d_in[8];
    const float* Wl2 = (const float*)d_in[9];
    const float* bl2 = (const float*)d_in[10];
    const float* Wr2 = (const float*)d_in[11];
    const float* br2 = (const float*)d_in[12];
    const float* att2= (const float*)d_in[13];
    const float* bo2 = (const float*)d_in[14];
    float* out = (float*)d_out;

    const int N = in_sizes[0] / 64;     // 100000
    const int E = in_sizes[1] / 2;      // 1600000
    const int TE = E + N;

    float *p_xl, *p_xr, *p_h;
    cudaGetSymbolAddress((void**)&p_xl, g_xl);
    cudaGetSymbolAddress((void**)&p_xr, g_xr);
    cudaGetSymbolAddress((void**)&p_h,  g_h);

    const int TB = 256;
    dim3 gemmGrid1(64 / 64, cdiv(N, 64));   // Ncol = 64
    dim3 gemmGrid2(256 / 64, cdiv(N, 64));  // Ncol = 256
    int edgeBlocks = cdiv(TE, TB / 32);     // one warp per edge
    int smBlocks   = cdiv(TE * HEADS, TB);

    // Edge-index dtype detection + int32 conversion (with self loops)
    detect_kernel<<<1, 1>>>(ei, 16, (long long)N);
    convert_edges_kernel<<<cdiv(TE, TB), TB>>>(ei, E, N);

    // ============ Layer 1: GATv2(64 -> 16, H=4, concat) ============
    gemm_bias_kernel<<<gemmGrid1, TB>>>(x, Wl1, bl1, p_xl, N, 64, 64);
    gemm_bias_kernel<<<gemmGrid1, TB>>>(x, Wr1, br1, p_xr, N, 64, 64);
    init_kernel<<<cdiv(N * 64, TB), TB>>>(N * 64, N * HEADS);
    edge_score_kernel<16><<<edgeBlocks, TB>>>(TE, att1);
    edge_softmax_kernel<<<smBlocks, TB>>>(TE);
    edge_agg_kernel<16><<<edgeBlocks, TB>>>(TE);
    finalize1_kernel<<<cdiv(N * 64, TB), TB>>>(bo1, N);

    // ============ Layer 2: GATv2(64 -> 64, H=4, mean) ============
    gemm_bias_kernel<<<gemmGrid2, TB>>>(p_h, Wl2, bl2, p_xl, N, 64, 256);
    gemm_bias_kernel<<<gemmGrid2, TB>>>(p_h, Wr2, br2, p_xr, N, 64, 256);
    init_kernel<<<cdiv(N * 256, TB), TB>>>(N * 256, N * HEADS);
    edge_score_kernel<64><<<edgeBlocks, TB>>>(TE, att2);
    edge_softmax_kernel<<<smBlocks, TB>>>(TE);
    edge_agg_kernel<64><<<edgeBlocks, TB>>>(TE);
    finalize2_kernel<<<cdiv(N * 64, TB), TB>>>(out, bo2, N);
}

// round 3
// speedup vs baseline: 5.1476x; 5.1476x over previous
#include <cuda_runtime.h>
#include <cuda_bf16.h>
#include <math_constants.h>

#define NNODES   100000
#define EEDGES   1600000
#define TEDGES   (EEDGES + NNODES)
#define NEG_SLOPE 0.2f
#define HEADS 4

// ---------------------------------------------------------------------------
// Device scratch (static; no cudaMalloc allowed)
// ---------------------------------------------------------------------------
__device__ float g_xl[NNODES * 256];
__device__ float g_xr[NNODES * 256];
__device__ float g_h [NNODES * 64];
__device__ int   g_src [TEDGES];
__device__ int   g_dst [TEDGES];
__device__ int   g_ssrc[TEDGES];        // src ids sorted by dst segment
__device__ int   g_cnt [NNODES];
__device__ int   g_cur [NNODES];
__device__ int   g_base[NNODES + 1];    // CSR row pointers (by dst)
__device__ int   g_bsum[128];
__device__ int   g_boff[128];
__device__ int   g_is64;

static inline int cdiv(int a, int b) { return (a + b - 1) / b; }

// ---------------------------------------------------------------------------
// Edge-index dtype detect (int64 vs int32)
// ---------------------------------------------------------------------------
__global__ void detect_kernel(const void* ei, int nCheck, long long nNodes) {
    const long long* p = (const long long*)ei;
    int ok = 1;
    for (int i = 0; i < nCheck; i++) {
        long long v = p[i];
        if (v < 0 || v >= nNodes) { ok = 0; break; }
    }
    g_is64 = ok;
}

// Convert to int32 src/dst (append self loops); also zero the histogram.
__global__ void convert_edges_kernel(const void* ei, int E, int Nn) {
    int i = blockIdx.x * blockDim.x + threadIdx.x;
    if (i < Nn) g_cnt[i] = 0;
    int total = E + Nn;
    if (i >= total) return;
    if (i < E) {
        if (g_is64) {
            const long long* p = (const long long*)ei;
            g_src[i] = (int)p[i];
            g_dst[i] = (int)p[E + i];
        } else {
            const int* p = (const int*)ei;
            g_src[i] = p[i];
            g_dst[i] = p[E + i];
        }
    } else {
        int n = i - E;
        g_src[i] = n;
        g_dst[i] = n;
    }
}

__global__ void hist_kernel(int total) {
    int i = blockIdx.x * blockDim.x + threadIdx.x;
    if (i < total) atomicAdd(&g_cnt[g_dst[i]], 1);
}

// ---------------------------------------------------------------------------
// 2-level exclusive scan over g_cnt[0..n) -> g_base
// ---------------------------------------------------------------------------
__global__ void scan1_kernel(int n) {
    __shared__ int sh[1024];
    int t = threadIdx.x;
    int i = blockIdx.x * 1024 + t;
    int v = (i < n) ? g_cnt[i] : 0;
    sh[t] = v;
    __syncthreads();
    for (int off = 1; off < 1024; off <<= 1) {
        int u = (t >= off) ? sh[t - off] : 0;
        __syncthreads();
        sh[t] += u;
        __syncthreads();
    }
    int incl = sh[t];
    if (i < n) g_base[i] = incl - v;          // block-local exclusive
    if (t == 1023) g_bsum[blockIdx.x] = incl; // block total
}

__global__ void scan2_kernel(int nb) {
    int lane = threadIdx.x;
    int carry = 0;
    for (int b = 0; b < nb; b += 32) {
        int i = b + lane;
        int orig = (i < nb) ? g_bsum[i] : 0;
        int v = orig;
        #pragma unroll
        for (int off = 1; off < 32; off <<= 1) {
            int u = __shfl_up_sync(0xffffffffu, v, off);
            if (lane >= off) v += u;
        }
        if (i < nb) g_boff[i] = carry + v - orig;
        carry += __shfl_sync(0xffffffffu, v, 31);
    }
}

__global__ void scan3_kernel(int n, int total) {
    int i = blockIdx.x * 1024 + threadIdx.x;
    if (i < n) {
        int b = g_base[i] + g_boff[blockIdx.x];
        g_base[i] = b;
        g_cur[i]  = b;
    }
    if (i == 0) g_base[n] = total;
}

__global__ void scatter_kernel(int total) {
    int i = blockIdx.x * blockDim.x + threadIdx.x;
    if (i >= total) return;
    int d = g_dst[i];
    int pos = atomicAdd(&g_cur[d], 1);
    g_ssrc[pos] = g_src[i];
}

// ---------------------------------------------------------------------------
// Tiled fp32 GEMM: C = A[M,K] @ W[K,Ncol] + bias
// ---------------------------------------------------------------------------
__global__ void gemm_bias_kernel(const float* __restrict__ A,
                                 const float* __restrict__ W,
                                 const float* __restrict__ bias,
                                 float* __restrict__ C,
                                 int M, int K, int Ncol) {
    __shared__ float As[16][65];
    __shared__ float Ws[16][65];
    const int tid = threadIdx.x;
    const int row0 = blockIdx.y * 64;
    const int col0 = blockIdx.x * 64;
    const int tx = tid & 15, ty = tid >> 4;
    float acc[4][4] = {};

    for (int k0 = 0; k0 < K; k0 += 16) {
        {
            int r = tid >> 2, c4 = (tid & 3) * 4;
            int row = row0 + r;
            float4 v = make_float4(0.f, 0.f, 0.f, 0.f);
            if (row < M)
                v = *reinterpret_cast<const float4*>(A + (size_t)row * K + k0 + c4);
            As[c4 + 0][r] = v.x; As[c4 + 1][r] = v.y;
            As[c4 + 2][r] = v.z; As[c4 + 3][r] = v.w;
        }
        {
            int kk = tid >> 4, c4 = (tid & 15) * 4;
            float4 v = *reinterpret_cast<const float4*>(W + (size_t)(k0 + kk) * Ncol + col0 + c4);
            Ws[kk][c4 + 0] = v.x; Ws[kk][c4 + 1] = v.y;
            Ws[kk][c4 + 2] = v.z; Ws[kk][c4 + 3] = v.w;
        }
        __syncthreads();
        #pragma unroll
        for (int kk = 0; kk < 16; kk++) {
            float am[4], wn[4];
            #pragma unroll
            for (int i = 0; i < 4; i++) am[i] = As[kk][ty * 4 + i];
            #pragma unroll
            for (int j = 0; j < 4; j++) wn[j] = Ws[kk][tx * 4 + j];
            #pragma unroll
            for (int i = 0; i < 4; i++)
                #pragma unroll
                for (int j = 0; j < 4; j++)
                    acc[i][j] += am[i] * wn[j];
        }
        __syncthreads();
    }
    #pragma unroll
    for (int i = 0; i < 4; i++) {
        int row = row0 + ty * 4 + i;
        if (row >= M) continue;
        #pragma unroll
        for (int j = 0; j < 4; j++) {
            int col = col0 + tx * 4 + j;
            C[(size_t)row * Ncol + col] = acc[i][j] + bias[col];
        }
    }
}

// ---------------------------------------------------------------------------
// Vector load helper
// ---------------------------------------------------------------------------
template<int PE>
__device__ __forceinline__ void loadVec(const float* __restrict__ p, float* v) {
    if constexpr (PE % 4 == 0) {
        #pragma unroll
        for (int j = 0; j < PE / 4; j++) {
            float4 t = __ldg(reinterpret_cast<const float4*>(p) + j);
            v[j * 4 + 0] = t.x; v[j * 4 + 1] = t.y;
            v[j * 4 + 2] = t.z; v[j * 4 + 3] = t.w;
        }
    } else {
        float2 t = __ldg(reinterpret_cast<const float2*>(p));
        v[0] = t.x; v[1] = t.y;
    }
}

// ---------------------------------------------------------------------------
// Fused GATv2 edge pass: warp per dst node, online softmax, no atomics.
// Lane layout: head h = lane>>3, PE = D/32 contiguous features per lane.
// ---------------------------------------------------------------------------
template<int CC, bool MEAN>
__global__ void fused_gat_kernel(const float* __restrict__ att,
                                 const float* __restrict__ bo,
                                 float* __restrict__ outp, int Nn) {
    constexpr int D = HEADS * CC;
    constexpr int PE = D / 32;
    int w = (blockIdx.x * blockDim.x + threadIdx.x) >> 5;
    int lane = threadIdx.x & 31;
    if (w >= Nn) return;

    const int f0 = lane * PE;
    const int beg = g_base[w];
    const int end = g_base[w + 1];

    float vr[PE], av[PE];
    loadVec<PE>(g_xr + (size_t)w * D + f0, vr);
    #pragma unroll
    for (int j = 0; j < PE; j++) av[j] = __ldg(att + f0 + j);

    float m = -CUDART_INF_F, l = 0.f;
    float acc[PE];
    #pragma unroll
    for (int j = 0; j < PE; j++) acc[j] = 0.f;

    // software pipeline: prefetch next edge's src features
    float vl[PE];
    if (beg < end) {
        int s0 = __ldg(g_ssrc + beg);
        loadVec<PE>(g_xl + (size_t)s0 * D + f0, vl);
    }

    for (int p = beg; p < end; p++) {
        float cvl[PE];
        #pragma unroll
        for (int j = 0; j < PE; j++) cvl[j] = vl[j];
        if (p + 1 < end) {
            int sn = __ldg(g_ssrc + p + 1);
            loadVec<PE>(g_xl + (size_t)sn * D + f0, vl);
        }
        float partial = 0.f;
        #pragma unroll
        for (int j = 0; j < PE; j++) {
            float v = cvl[j] + vr[j];
            v = (v > 0.f) ? v : NEG_SLOPE * v;
            partial = fmaf(av[j], v, partial);
        }
        // butterfly sum within 8-lane head group -> every lane has its head score
        #pragma unroll
        for (int off = 4; off; off >>= 1)
            partial += __shfl_xor_sync(0xffffffffu, partial, off);

        float mn = fmaxf(m, partial);
        float scale = __expf(m - mn);        // exp(-inf)=0 on first edge
        float pe = __expf(partial - mn);
        l = l * scale + pe;
        #pragma unroll
        for (int j = 0; j < PE; j++)
            acc[j] = acc[j] * scale + pe * cvl[j];
        m = mn;
    }

    float inv = 1.f / (l + 1e-16f);

    if constexpr (!MEAN) {
        // concat layout == flat [H*C]; add bias + relu (layer-1 epilogue)
        float2 o;
        o.x = acc[0] * inv + __ldg(bo + f0 + 0);
        o.y = acc[1] * inv + __ldg(bo + f0 + 1);
        o.x = (o.x > 0.f) ? o.x : 0.f;
        o.y = (o.y > 0.f) ? o.y : 0.f;
        *reinterpret_cast<float2*>(outp + (size_t)w * D + f0) = o;
    } else {
        #pragma unroll
        for (int j = 0; j < PE; j++) acc[j] *= inv;
        // sum across the 4 head groups (lane bits 3,4)
        #pragma unroll
        for (int j = 0; j < PE; j++) {
            acc[j] += __shfl_xor_sync(0xffffffffu, acc[j], 8);
            acc[j] += __shfl_xor_sync(0xffffffffu, acc[j], 16);
        }
        if (lane < 8) {   // lanes 0..7 hold features f0..f0+7 (f0 = lane*8 < 64)
            float o[PE];
            #pragma unroll
            for (int j = 0; j < PE; j++) {
                float v = 0.25f * acc[j] + __ldg(bo + f0 + j);
                o[j] = (v > 0.f) ? v : 0.f;
            }
            #pragma unroll
            for (int j = 0; j < PE / 4; j++)
                *reinterpret_cast<float4*>(outp + (size_t)w * 64 + f0 + j * 4) =
                    make_float4(o[j*4], o[j*4+1], o[j*4+2], o[j*4+3]);
        }
    }
}

// ---------------------------------------------------------------------------
// Host launcher
// ---------------------------------------------------------------------------
extern "C" void kernel_launch(void* const* d_in, const int* in_sizes, int n_in,
                              void* d_out, int out_size) {
    const float* x   = (const float*)d_in[0];
    const void*  ei  = d_in[1];
    const float* Wl1 = (const float*)d_in[3];
    const float* bl1 = (const float*)d_in[4];
    const float* Wr1 = (const float*)d_in[5];
    const float* br1 = (const float*)d_in[6];
    const float* att1= (const float*)d_in[7];
    const float* bo1 = (const float*)d_in[8];
    const float* Wl2 = (const float*)d_in[9];
    const float* bl2 = (const float*)d_in[10];
    const float* Wr2 = (const float*)d_in[11];
    const float* br2 = (const float*)d_in[12];
    const float* att2= (const float*)d_in[13];
    const float* bo2 = (const float*)d_in[14];
    float* out = (float*)d_out;

    const int N = in_sizes[0] / 64;
    const int E = in_sizes[1] / 2;
    const int TE = E + N;

    float *p_xl, *p_xr, *p_h;
    cudaGetSymbolAddress((void**)&p_xl, g_xl);
    cudaGetSymbolAddress((void**)&p_xr, g_xr);
    cudaGetSymbolAddress((void**)&p_h,  g_h);

    const int TB = 256;
    dim3 gemmGrid1(1, cdiv(N, 64));
    dim3 gemmGrid2(4, cdiv(N, 64));
    int fusedBlocks = cdiv(N, TB / 32);
    int nScanBlocks = cdiv(N, 1024);

    // ---- build dst-sorted edge CSR ----
    detect_kernel<<<1, 1>>>(ei, 16, (long long)N);
    convert_edges_kernel<<<cdiv(TE, TB), TB>>>(ei, E, N);
    hist_kernel<<<cdiv(TE, TB), TB>>>(TE);
    scan1_kernel<<<nScanBlocks, 1024>>>(N);
    scan2_kernel<<<1, 32>>>(nScanBlocks);
    scan3_kernel<<<nScanBlocks, 1024>>>(N, TE);
    scatter_kernel<<<cdiv(TE, TB), TB>>>(TE);

    // ---- layer 1: GATv2(64 -> 16, H=4, concat) + relu ----
    gemm_bias_kernel<<<gemmGrid1, TB>>>(x, Wl1, bl1, p_xl, N, 64, 64);
    gemm_bias_kernel<<<gemmGrid1, TB>>>(x, Wr1, br1, p_xr, N, 64, 64);
    fused_gat_kernel<16, false><<<fusedBlocks, TB>>>(att1, bo1, p_h, N);

    // ---- layer 2: GATv2(64 -> 64, H=4, mean) + relu ----
    gemm_bias_kernel<<<gemmGrid2, TB>>>(p_h, Wl2, bl2, p_xl, N, 64, 256);
    gemm_bias_kernel<<<gemmGrid2, TB>>>(p_h, Wr2, br2, p_xr, N, 64, 256);
    fused_gat_kernel<64, true><<<fusedBlocks, TB>>>(att2, bo2, out, N);
}

// round 4
// speedup vs baseline: 6.1837x; 1.2013x over previous
#include <cuda_runtime.h>
#include <cuda_bf16.h>
#include <math_constants.h>

#define NNODES   100000
#define EEDGES   1600000
#define TEDGES   (EEDGES + NNODES)
#define NEG_SLOPE 0.2f
#define HEADS 4

// ---------------------------------------------------------------------------
// Device scratch (static; no cudaMalloc allowed)
// ---------------------------------------------------------------------------
__device__ float g_xl[NNODES * 256];
__device__ float g_xr[NNODES * 256];
__device__ float g_h [NNODES * 64];
__device__ int   g_src [TEDGES];
__device__ int   g_dst [TEDGES];
__device__ int   g_ssrc[TEDGES];
__device__ int   g_cnt [NNODES];
__device__ int   g_cur [NNODES];
__device__ int   g_base[NNODES + 1];
__device__ int   g_bsum[128];
__device__ int   g_boff[128];
__device__ int   g_is64;

static inline int cdiv(int a, int b) { return (a + b - 1) / b; }

// ---------------------------------------------------------------------------
// Edge-index dtype detect + CSR build (unchanged from R2)
// ---------------------------------------------------------------------------
__global__ void detect_kernel(const void* ei, int nCheck, long long nNodes) {
    const long long* p = (const long long*)ei;
    int ok = 1;
    for (int i = 0; i < nCheck; i++) {
        long long v = p[i];
        if (v < 0 || v >= nNodes) { ok = 0; break; }
    }
    g_is64 = ok;
}

__global__ void convert_edges_kernel(const void* ei, int E, int Nn) {
    int i = blockIdx.x * blockDim.x + threadIdx.x;
    if (i < Nn) g_cnt[i] = 0;
    int total = E + Nn;
    if (i >= total) return;
    if (i < E) {
        if (g_is64) {
            const long long* p = (const long long*)ei;
            g_src[i] = (int)p[i];
            g_dst[i] = (int)p[E + i];
        } else {
            const int* p = (const int*)ei;
            g_src[i] = p[i];
            g_dst[i] = p[E + i];
        }
    } else {
        int n = i - E;
        g_src[i] = n;
        g_dst[i] = n;
    }
}

__global__ void hist_kernel(int total) {
    int i = blockIdx.x * blockDim.x + threadIdx.x;
    if (i < total) atomicAdd(&g_cnt[g_dst[i]], 1);
}

__global__ void scan1_kernel(int n) {
    __shared__ int sh[1024];
    int t = threadIdx.x;
    int i = blockIdx.x * 1024 + t;
    int v = (i < n) ? g_cnt[i] : 0;
    sh[t] = v;
    __syncthreads();
    for (int off = 1; off < 1024; off <<= 1) {
        int u = (t >= off) ? sh[t - off] : 0;
        __syncthreads();
        sh[t] += u;
        __syncthreads();
    }
    int incl = sh[t];
    if (i < n) g_base[i] = incl - v;
    if (t == 1023) g_bsum[blockIdx.x] = incl;
}

__global__ void scan2_kernel(int nb) {
    int lane = threadIdx.x;
    int carry = 0;
    for (int b = 0; b < nb; b += 32) {
        int i = b + lane;
        int orig = (i < nb) ? g_bsum[i] : 0;
        int v = orig;
        #pragma unroll
        for (int off = 1; off < 32; off <<= 1) {
            int u = __shfl_up_sync(0xffffffffu, v, off);
            if (lane >= off) v += u;
        }
        if (i < nb) g_boff[i] = carry + v - orig;
        carry += __shfl_sync(0xffffffffu, v, 31);
    }
}

__global__ void scan3_kernel(int n, int total) {
    int i = blockIdx.x * 1024 + threadIdx.x;
    if (i < n) {
        int b = g_base[i] + g_boff[blockIdx.x];
        g_base[i] = b;
        g_cur[i]  = b;
    }
    if (i == 0) g_base[n] = total;
}

__global__ void scatter_kernel(int total) {
    int i = blockIdx.x * blockDim.x + threadIdx.x;
    if (i >= total) return;
    int d = g_dst[i];
    int pos = atomicAdd(&g_cur[d], 1);
    g_ssrc[pos] = g_src[i];
}

// ---------------------------------------------------------------------------
// tf32 mma helpers (3xTF32 split for fp32-grade accuracy)
// ---------------------------------------------------------------------------
__device__ __forceinline__ unsigned f2tf32(float x) {
    unsigned u;
    asm("cvt.rna.tf32.f32 %0, %1;" : "=r"(u) : "f"(x));
    return u;
}

__device__ __forceinline__ void mma_m16n8k8(float* d, const unsigned* a, const unsigned* b) {
    asm volatile(
        "mma.sync.aligned.m16n8k8.row.col.f32.tf32.tf32.f32 "
        "{%0,%1,%2,%3}, {%4,%5,%6,%7}, {%8,%9}, {%0,%1,%2,%3};\n"
        : "+f"(d[0]), "+f"(d[1]), "+f"(d[2]), "+f"(d[3])
        : "r"(a[0]), "r"(a[1]), "r"(a[2]), "r"(a[3]),
          "r"(b[0]), "r"(b[1]));
}

// ---------------------------------------------------------------------------
// Dual GEMM (tensor cores, 3xTF32): computes BOTH  Cl = A@Wl + bl  and
// Cr = A@Wr + br  in one grid. K=64 fixed. BM=128, BN=64, 256 threads.
// Block x covers global columns [x*64, x*64+64) of the concatenated [Wl|Wr];
// since 64 | Nc, each block uniformly targets one of the two outputs.
// ---------------------------------------------------------------------------
__global__ void dual_gemm_tf32(const float* __restrict__ A,
                               const float* __restrict__ Wl, const float* __restrict__ bl,
                               const float* __restrict__ Wr, const float* __restrict__ br,
                               float* __restrict__ Cl, float* __restrict__ Cr,
                               int M, int Nc) {
    extern __shared__ float sm[];
    float* As = sm;               // [128][65]
    float* Bs = sm + 128 * 65;    // [64][65]  stored as [n][k]
    const int tid  = threadIdx.x;
    const int warp = tid >> 5, lane = tid & 31;
    const int g = lane >> 2, c = lane & 3;
    const int row0 = blockIdx.y * 128;
    const int col0 = blockIdx.x * 64;

    const float* W; const float* bias; float* C; int cofs;
    if (col0 < Nc) { W = Wl; bias = bl; C = Cl; cofs = col0; }
    else           { W = Wr; bias = br; C = Cr; cofs = col0 - Nc; }

    // A tile: 128 rows x 64 cols (float4 loads, guard rows)
    #pragma unroll
    for (int i = 0; i < 8; i++) {
        int idx = tid + i * 256;          // float4 index; 16 float4 per row
        int r = idx >> 4, c4 = (idx & 15) << 2;
        int row = row0 + r;
        float4 v = make_float4(0.f, 0.f, 0.f, 0.f);
        if (row < M)
            v = *reinterpret_cast<const float4*>(A + (size_t)row * 64 + c4);
        float* dst = As + r * 65 + c4;
        dst[0] = v.x; dst[1] = v.y; dst[2] = v.z; dst[3] = v.w;
    }
    // B tile: W[k=0..63][cofs..cofs+63] -> Bs[n][k] (transposed)
    #pragma unroll
    for (int i = 0; i < 4; i++) {
        int idx = tid + i * 256;
        int k = idx >> 4, c4 = (idx & 15) << 2;
        float4 v = *reinterpret_cast<const float4*>(W + (size_t)k * Nc + cofs + c4);
        Bs[(c4 + 0) * 65 + k] = v.x;
        Bs[(c4 + 1) * 65 + k] = v.y;
        Bs[(c4 + 2) * 65 + k] = v.z;
        Bs[(c4 + 3) * 65 + k] = v.w;
    }
    __syncthreads();

    float acc[8][4];
    #pragma unroll
    for (int n = 0; n < 8; n++)
        #pragma unroll
        for (int j = 0; j < 4; j++) acc[n][j] = 0.f;

    const int wr = warp * 16;
    #pragma unroll
    for (int kk = 0; kk < 8; kk++) {
        const int k0 = kk * 8;
        float a_f[4];
        a_f[0] = As[(wr + g)     * 65 + k0 + c];
        a_f[1] = As[(wr + g + 8) * 65 + k0 + c];
        a_f[2] = As[(wr + g)     * 65 + k0 + c + 4];
        a_f[3] = As[(wr + g + 8) * 65 + k0 + c + 4];
        unsigned ahi[4], alo[4];
        #pragma unroll
        for (int j = 0; j < 4; j++) {
            ahi[j] = f2tf32(a_f[j]);
            alo[j] = f2tf32(a_f[j] - __uint_as_float(ahi[j]));
        }
        #pragma unroll
        for (int n = 0; n < 8; n++) {
            float b0 = Bs[(n * 8 + g) * 65 + k0 + c];
            float b1 = Bs[(n * 8 + g) * 65 + k0 + c + 4];
            unsigned bhi[2], blo[2];
            bhi[0] = f2tf32(b0);
            bhi[1] = f2tf32(b1);
            blo[0] = f2tf32(b0 - __uint_as_float(bhi[0]));
            blo[1] = f2tf32(b1 - __uint_as_float(bhi[1]));
            mma_m16n8k8(acc[n], ahi, bhi);
            mma_m16n8k8(acc[n], alo, bhi);
            mma_m16n8k8(acc[n], ahi, blo);
        }
    }

    // epilogue: C[r][col] = acc + bias
    #pragma unroll
    for (int n = 0; n < 8; n++) {
        int colg = cofs + n * 8 + 2 * c;
        float bx = __ldg(bias + colg);
        float by = __ldg(bias + colg + 1);
        int r1 = row0 + wr + g, r2 = r1 + 8;
        if (r1 < M)
            *reinterpret_cast<float2*>(C + (size_t)r1 * Nc + colg) =
                make_float2(acc[n][0] + bx, acc[n][1] + by);
        if (r2 < M)
            *reinterpret_cast<float2*>(C + (size_t)r2 * Nc + colg) =
                make_float2(acc[n][2] + bx, acc[n][3] + by);
    }
}

// ---------------------------------------------------------------------------
// Vector load helper
// ---------------------------------------------------------------------------
template<int PE>
__device__ __forceinline__ void loadVec(const float* __restrict__ p, float* v) {
    if constexpr (PE % 4 == 0) {
        #pragma unroll
        for (int j = 0; j < PE / 4; j++) {
            float4 t = __ldg(reinterpret_cast<const float4*>(p) + j);
            v[j * 4 + 0] = t.x; v[j * 4 + 1] = t.y;
            v[j * 4 + 2] = t.z; v[j * 4 + 3] = t.w;
        }
    } else {
        float2 t = __ldg(reinterpret_cast<const float2*>(p));
        v[0] = t.x; v[1] = t.y;
    }
}

// ---------------------------------------------------------------------------
// Fused GATv2 edge pass: warp per dst node, online softmax, no atomics.
// ---------------------------------------------------------------------------
template<int CC, bool MEAN>
__global__ void fused_gat_kernel(const float* __restrict__ att,
                                 const float* __restrict__ bo,
                                 float* __restrict__ outp, int Nn) {
    constexpr int D = HEADS * CC;
    constexpr int PE = D / 32;
    int w = (blockIdx.x * blockDim.x + threadIdx.x) >> 5;
    int lane = threadIdx.x & 31;
    if (w >= Nn) return;

    const int f0 = lane * PE;
    const int beg = g_base[w];
    const int end = g_base[w + 1];

    float vr[PE], av[PE];
    loadVec<PE>(g_xr + (size_t)w * D + f0, vr);
    #pragma unroll
    for (int j = 0; j < PE; j++) av[j] = __ldg(att + f0 + j);

    float m = -CUDART_INF_F, l = 0.f;
    float acc[PE];
    #pragma unroll
    for (int j = 0; j < PE; j++) acc[j] = 0.f;

    float vl[PE];
    if (beg < end) {
        int s0 = __ldg(g_ssrc + beg);
        loadVec<PE>(g_xl + (size_t)s0 * D + f0, vl);
    }

    for (int p = beg; p < end; p++) {
        float cvl[PE];
        #pragma unroll
        for (int j = 0; j < PE; j++) cvl[j] = vl[j];
        if (p + 1 < end) {
            int sn = __ldg(g_ssrc + p + 1);
            loadVec<PE>(g_xl + (size_t)sn * D + f0, vl);
        }
        float partial = 0.f;
        #pragma unroll
        for (int j = 0; j < PE; j++) {
            float v = cvl[j] + vr[j];
            v = (v > 0.f) ? v : NEG_SLOPE * v;
            partial = fmaf(av[j], v, partial);
        }
        #pragma unroll
        for (int off = 4; off; off >>= 1)
            partial += __shfl_xor_sync(0xffffffffu, partial, off);

        float mn = fmaxf(m, partial);
        float scale = __expf(m - mn);
        float pe = __expf(partial - mn);
        l = l * scale + pe;
        #pragma unroll
        for (int j = 0; j < PE; j++)
            acc[j] = acc[j] * scale + pe * cvl[j];
        m = mn;
    }

    float inv = 1.f / (l + 1e-16f);

    if constexpr (!MEAN) {
        float2 o;
        o.x = acc[0] * inv + __ldg(bo + f0 + 0);
        o.y = acc[1] * inv + __ldg(bo + f0 + 1);
        o.x = (o.x > 0.f) ? o.x : 0.f;
        o.y = (o.y > 0.f) ? o.y : 0.f;
        *reinterpret_cast<float2*>(outp + (size_t)w * D + f0) = o;
    } else {
        #pragma unroll
        for (int j = 0; j < PE; j++) acc[j] *= inv;
        #pragma unroll
        for (int j = 0; j < PE; j++) {
            acc[j] += __shfl_xor_sync(0xffffffffu, acc[j], 8);
            acc[j] += __shfl_xor_sync(0xffffffffu, acc[j], 16);
        }
        if (lane < 8) {
            float o[PE];
            #pragma unroll
            for (int j = 0; j < PE; j++) {
                float v = 0.25f * acc[j] + __ldg(bo + f0 + j);
                o[j] = (v > 0.f) ? v : 0.f;
            }
            #pragma unroll
            for (int j = 0; j < PE / 4; j++)
                *reinterpret_cast<float4*>(outp + (size_t)w * 64 + f0 + j * 4) =
                    make_float4(o[j*4], o[j*4+1], o[j*4+2], o[j*4+3]);
        }
    }
}

// ---------------------------------------------------------------------------
// Host launcher
// ---------------------------------------------------------------------------
extern "C" void kernel_launch(void* const* d_in, const int* in_sizes, int n_in,
                              void* d_out, int out_size) {
    const float* x   = (const float*)d_in[0];
    const void*  ei  = d_in[1];
    const float* Wl1 = (const float*)d_in[3];
    const float* bl1 = (const float*)d_in[4];
    const float* Wr1 = (const float*)d_in[5];
    const float* br1 = (const float*)d_in[6];
    const float* att1= (const float*)d_in[7];
    const float* bo1 = (const float*)d_in[8];
    const float* Wl2 = (const float*)d_in[9];
    const float* bl2 = (const float*)d_in[10];
    const float* Wr2 = (const float*)d_in[11];
    const float* br2 = (const float*)d_in[12];
    const float* att2= (const float*)d_in[13];
    const float* bo2 = (const float*)d_in[14];
    float* out = (float*)d_out;

    const int N = in_sizes[0] / 64;
    const int E = in_sizes[1] / 2;
    const int TE = E + N;

    float *p_xl, *p_xr, *p_h;
    cudaGetSymbolAddress((void**)&p_xl, g_xl);
    cudaGetSymbolAddress((void**)&p_xr, g_xr);
    cudaGetSymbolAddress((void**)&p_h,  g_h);

    const int TB = 256;
    const int SMEM_GEMM = (128 * 65 + 64 * 65) * 4;   // 49920 B
    cudaFuncSetAttribute(dual_gemm_tf32,
                         cudaFuncAttributeMaxDynamicSharedMemorySize, SMEM_GEMM);

    int fusedBlocks = cdiv(N, TB / 32);
    int nScanBlocks = cdiv(N, 1024);

    // ---- build dst-sorted edge CSR ----
    detect_kernel<<<1, 1>>>(ei, 16, (long long)N);
    convert_edges_kernel<<<cdiv(TE, TB), TB>>>(ei, E, N);
    hist_kernel<<<cdiv(TE, TB), TB>>>(TE);
    scan1_kernel<<<nScanBlocks, 1024>>>(N);
    scan2_kernel<<<1, 32>>>(nScanBlocks);
    scan3_kernel<<<nScanBlocks, 1024>>>(N, TE);
    scatter_kernel<<<cdiv(TE, TB), TB>>>(TE);

    // ---- layer 1: dual GEMM (Nc=64) + fused GAT ----
    dim3 g1(2, cdiv(N, 128));
    dual_gemm_tf32<<<g1, TB, SMEM_GEMM>>>(x, Wl1, bl1, Wr1, br1, p_xl, p_xr, N, 64);
    fused_gat_kernel<16, false><<<fusedBlocks, TB>>>(att1, bo1, p_h, N);

    // ---- layer 2: dual GEMM (Nc=256) + fused GAT ----
    dim3 g2(8, cdiv(N, 128));
    dual_gemm_tf32<<<g2, TB, SMEM_GEMM>>>(p_h, Wl2, bl2, Wr2, br2, p_xl, p_xr, N, 256);
    fused_gat_kernel<64, true><<<fusedBlocks, TB>>>(att2, bo2, out, N);
}